// round 5
// baseline (speedup 1.0000x reference)
#include <cuda_runtime.h>
#include <cstdint>

// out[b,f] = -( sum_w x[b,w,f] * W[f,w] + bias[f] )
// x: [512, 5, 25000] f32   W: [25000, 5] f32   bias: [25000] f32   out: [512, 25000] f32
//
// R5 = R4 with the w_s indexing bug fixed: w_s[p][tid] = W[f*5+p] linearly,
// so feature f uses w_s[wi], feature f+1 uses w_s[WS+wi].
// float2 granularity (2 features/thread), ~28 regs -> 8 CTAs/SM.

#define F_DIM    25000
#define WS       5
#define B_DIM    512
#define B_PER    2
#define NTHREADS 256
#define F2_DIM   (F_DIM / 2)   // 12500

__global__ __launch_bounds__(NTHREADS, 8)
void ocsvm_kernel(const float* __restrict__ x,
                  const float* __restrict__ W,
                  const float* __restrict__ bias,
                  float* __restrict__ out) {
    // w_s[p][tid] = W[f*5 + p], p in [0,10). 4B stride across threads ->
    // bank = tid%32: conflict-free.
    __shared__ float w_s[2 * WS][NTHREADS];

    const int tid = threadIdx.x;
    const int f2  = blockIdx.x * NTHREADS + tid;
    if (f2 >= F2_DIM) return;   // each thread only touches its own smem column
    const int f = f2 * 2;

    // This thread's 10 W floats are contiguous: W[f*5 .. f*5+10).
    {
        const float2* W2 = reinterpret_cast<const float2*>(W) + (size_t)f2 * WS;
#pragma unroll
        for (int k = 0; k < WS; k++) {
            float2 q = __ldg(W2 + k);
            w_s[2 * k + 0][tid] = q.x;   // = W[f*5 + 2k]
            w_s[2 * k + 1][tid] = q.y;   // = W[f*5 + 2k + 1]
        }
    }
    const float2 bb = __ldg(reinterpret_cast<const float2*>(bias + f));
    const float nb0 = -bb.x, nb1 = -bb.y;

    const int b0 = blockIdx.y * B_PER;

#pragma unroll 1   // re-read W from smem each iteration (keep regs low)
    for (int bi = 0; bi < B_PER; bi++) {
        const size_t base = (size_t)(b0 + bi) * (WS * F_DIM) + f;

        // 5 independent streaming loads in flight.
        float2 xv[WS];
#pragma unroll
        for (int wi = 0; wi < WS; wi++) {
            xv[wi] = __ldcs(reinterpret_cast<const float2*>(x + base + (size_t)wi * F_DIM));
        }

        float a0 = nb0, a1 = nb1;
#pragma unroll
        for (int wi = 0; wi < WS; wi++) {
            // feature f:   W[f*5  + wi] = w_s[wi]
            // feature f+1: W[(f+1)*5 + wi] = w_s[WS + wi]
            a0 = fmaf(-xv[wi].x, w_s[wi][tid],      a0);
            a1 = fmaf(-xv[wi].y, w_s[WS + wi][tid], a1);
        }

        float2 o; o.x = a0; o.y = a1;
        __stcs(reinterpret_cast<float2*>(out + (size_t)(b0 + bi) * F_DIM + f), o);
    }
}

extern "C" void kernel_launch(void* const* d_in, const int* in_sizes, int n_in,
                              void* d_out, int out_size) {
    const float* x    = (const float*)d_in[0];
    const float* W    = (const float*)d_in[1];
    const float* bias = (const float*)d_in[2];
    float* out        = (float*)d_out;

    dim3 grid((F2_DIM + NTHREADS - 1) / NTHREADS,   // 49
              B_DIM / B_PER);                        // 256
    ocsvm_kernel<<<grid, NTHREADS>>>(x, W, bias, out);
}

// round 6
// speedup vs baseline: 1.0879x; 1.0879x over previous
#include <cuda_runtime.h>
#include <cstdint>

// out[b,f] = -( sum_w x[b,w,f] * W[f,w] + bias[f] )
// x: [512, 5, 25000] f32   W: [25000, 5] f32   bias: [25000] f32   out: [512, 25000] f32
//
// R6: float4 granularity, both batch rows' loads issued up front:
// 10 independent LDG.128 per thread (160 B in flight) before any FMA.
// 4 CTAs/SM x 256 thr x 160 B = 160 KB in-flight per SM (vs 120 KB in R3).
// W/bias in conflict-free per-thread SMEM columns; .cs hints on x/out.

#define F_DIM    25000
#define WS       5
#define B_DIM    512
#define B_PER    2
#define NTHREADS 256
#define F4_DIM   (F_DIM / 4)   // 6250

__global__ __launch_bounds__(NTHREADS, 4)
void ocsvm_kernel(const float* __restrict__ x,
                  const float* __restrict__ W,
                  const float* __restrict__ bias,
                  float* __restrict__ out) {
    // w_s[p][tid] holds W[(f + p/5)*5 + p%5]; 4B stride across threads ->
    // bank = tid%32: conflict-free.
    __shared__ float w_s[4 * WS][NTHREADS];

    const int tid = threadIdx.x;
    const int f4  = blockIdx.x * NTHREADS + tid;
    if (f4 >= F4_DIM) return;   // each thread only touches its own smem column
    const int f = f4 * 4;

    // This thread's 20 W floats are contiguous: W[f*5 .. f*5+20) = 5 x float4.
    {
        const float4* W4 = reinterpret_cast<const float4*>(W) + (size_t)f4 * WS;
#pragma unroll
        for (int k = 0; k < WS; k++) {
            float4 q = __ldg(W4 + k);
            w_s[4 * k + 0][tid] = q.x;
            w_s[4 * k + 1][tid] = q.y;
            w_s[4 * k + 2][tid] = q.z;
            w_s[4 * k + 3][tid] = q.w;
        }
    }
    const float4 bb = __ldg(reinterpret_cast<const float4*>(bias + f));
    const float nb0 = -bb.x, nb1 = -bb.y, nb2 = -bb.z, nb3 = -bb.w;

    const int b0 = blockIdx.y * B_PER;

    // Issue ALL 10 streaming loads (both rows) before any math: MLP = 10.
    float4 xv[B_PER][WS];
#pragma unroll
    for (int bi = 0; bi < B_PER; bi++) {
        const size_t base = (size_t)(b0 + bi) * (WS * F_DIM) + f;
#pragma unroll
        for (int wi = 0; wi < WS; wi++) {
            xv[bi][wi] = __ldcs(reinterpret_cast<const float4*>(x + base + (size_t)wi * F_DIM));
        }
    }

#pragma unroll
    for (int bi = 0; bi < B_PER; bi++) {
        float a0 = nb0, a1 = nb1, a2 = nb2, a3 = nb3;
#pragma unroll
        for (int wi = 0; wi < WS; wi++) {
            a0 = fmaf(-xv[bi][wi].x, w_s[0 * WS + wi][tid], a0);
            a1 = fmaf(-xv[bi][wi].y, w_s[1 * WS + wi][tid], a1);
            a2 = fmaf(-xv[bi][wi].z, w_s[2 * WS + wi][tid], a2);
            a3 = fmaf(-xv[bi][wi].w, w_s[3 * WS + wi][tid], a3);
        }
        float4 o; o.x = a0; o.y = a1; o.z = a2; o.w = a3;
        __stcs(reinterpret_cast<float4*>(out + (size_t)(b0 + bi) * F_DIM + f), o);
    }
}

extern "C" void kernel_launch(void* const* d_in, const int* in_sizes, int n_in,
                              void* d_out, int out_size) {
    const float* x    = (const float*)d_in[0];
    const float* W    = (const float*)d_in[1];
    const float* bias = (const float*)d_in[2];
    float* out        = (float*)d_out;

    dim3 grid((F4_DIM + NTHREADS - 1) / NTHREADS,   // 25
              B_DIM / B_PER);                        // 256
    ocsvm_kernel<<<grid, NTHREADS>>>(x, W, bias, out);
}